// round 1
// baseline (speedup 1.0000x reference)
#include <cuda_runtime.h>
#include <cstdint>

// Problem constants
#define Bq 16384
#define Dq 17
#define Hq 256
#define Eq 64
#define NHq 4
#define SLOPE 0.01f

typedef unsigned long long ull;

// Scratch: tokens (B, D, E) fp32 = 71.3 MB
__device__ float g_tokens[(size_t)Bq * Dq * Eq];
// Folded epilogue weights
__device__ __align__(16) float g_gvec[Eq];
__device__ __align__(16) float g_wvg[NHq * Eq];
__device__ float g_bvg[NHq];
__device__ float g_c0[1];

__device__ __forceinline__ float lrelu(float v) { return v >= 0.f ? v : SLOPE * v; }

// ---------------------------------------------------------------------------
// Precompute: g[f] = sum_e Wo[e,f]*Wfc[e]; c0 = sum_e bo[e]*Wfc[e]
//             wvg[h,f] = sum_c Wv[16h+c,f]*g[16h+c]; bvg[h] = sum_c bv[16h+c]*g[16h+c]
// ---------------------------------------------------------------------------
__global__ void precompute_kernel(const float* __restrict__ Wo, const float* __restrict__ bo,
                                  const float* __restrict__ Wfc, const float* __restrict__ Wv,
                                  const float* __restrict__ bv) {
    __shared__ float gs[Eq];
    int t = threadIdx.x;
    if (t < Eq) {
        float s = 0.f;
        for (int e = 0; e < Eq; e++) s += Wo[e * Eq + t] * Wfc[e];
        gs[t] = s;
        g_gvec[t] = s;
    }
    if (t == Eq) {
        float s = 0.f;
        for (int e = 0; e < Eq; e++) s += bo[e] * Wfc[e];
        g_c0[0] = s;
    }
    __syncthreads();
    {
        int h = t >> 6, f = t & 63;
        float s = 0.f;
        for (int c = 0; c < 16; c++) s += Wv[(h * 16 + c) * Eq + f] * gs[h * 16 + c];
        g_wvg[t] = s;
    }
    if (t < NHq) {
        float s = 0.f;
        for (int c = 0; c < 16; c++) s += bv[t * 16 + c] * gs[t * 16 + c];
        g_bvg[t] = s;
    }
}

// ---------------------------------------------------------------------------
// Subnet kernel: grid (B/64, 17), block 256.
// SMEM: hA[64][256] fp32 (64KB) + Ws[32][256] fp32 (32KB) = 96KB dyn.
// Per-thread 8x8 register tile, packed f32x2 FMAs.
// ---------------------------------------------------------------------------
#define TB 64
#define SMEM_SUBNET ((TB * Hq + 32 * Hq) * 4)

__global__ __launch_bounds__(256, 2) void subnet_kernel(
    const float* __restrict__ x, const float* __restrict__ W1, const float* __restrict__ b1,
    const float* __restrict__ Wm, const float* __restrict__ bm,
    const float* __restrict__ Wf, const float* __restrict__ bf) {
    extern __shared__ __align__(16) float smem[];
    float* hA = smem;              // [64][256]
    float* Ws = smem + TB * Hq;    // [32][256]
    __shared__ float xs[TB];

    const int i = blockIdx.y;
    const int rb = blockIdx.x * TB;
    const int tid = threadIdx.x;
    const int ty = tid >> 5;   // warp id -> row group (8 rows)
    const int tx = tid & 31;   // lane   -> col group (8 cols)

    if (tid < TB) xs[tid] = x[(size_t)(rb + tid) * Dq + i];
    __syncthreads();

    // ---- Layer 0: outer product + bias + lrelu ----
    {
        const float* w1 = W1 + i * Hq;
        const float* bb = b1 + i * Hq;
        #pragma unroll 4
        for (int idx = tid; idx < TB * Hq; idx += 256) {
            int r = idx >> 8, c = idx & 255;
            hA[idx] = lrelu(fmaf(xs[r], w1[c], bb[c]));
        }
    }
    __syncthreads();

    // ---- Two middle layers: 64x256 @ 256x256, lrelu ----
    for (int l = 0; l < 2; l++) {
        const float* W = Wm + (((size_t)l * Dq + i) << 16);   // 256*256 per (l,i)
        const float* bb = bm + ((l * Dq + i) << 8);
        const int r0 = ty * 8, o0 = tx * 8;

        ull acc[8][4];
        #pragma unroll
        for (int rr = 0; rr < 8; rr++)
            #pragma unroll
            for (int cp = 0; cp < 4; cp++) acc[rr][cp] = 0ull;

        for (int kb = 0; kb < Hq; kb += 32) {
            // Stage W[kb:kb+32][0:256] into SMEM (coalesced float4)
            const float4* Wg = (const float4*)(W + (size_t)kb * Hq);
            float4* Ws4 = (float4*)Ws;
            #pragma unroll
            for (int j = 0; j < 8; j++) Ws4[tid + j * 256] = Wg[tid + j * 256];
            __syncthreads();

            #pragma unroll 8
            for (int kk = 0; kk < 32; kk++) {
                ull ap[8];
                #pragma unroll
                for (int rr = 0; rr < 8; rr++) {
                    unsigned av = __float_as_uint(hA[(r0 + rr) * Hq + kb + kk]);
                    asm("mov.b64 %0, {%1,%1};" : "=l"(ap[rr]) : "r"(av));
                }
                ulonglong2 wA = *(const ulonglong2*)(Ws + kk * Hq + o0);
                ulonglong2 wB = *(const ulonglong2*)(Ws + kk * Hq + o0 + 4);
                ull wv[4] = {wA.x, wA.y, wB.x, wB.y};
                #pragma unroll
                for (int rr = 0; rr < 8; rr++)
                    #pragma unroll
                    for (int cp = 0; cp < 4; cp++)
                        asm("fma.rn.f32x2 %0, %1, %2, %0;"
                            : "+l"(acc[rr][cp]) : "l"(ap[rr]), "l"(wv[cp]));
            }
            __syncthreads();
        }

        // bias + lrelu + writeback into hA (all reads finished above)
        float bias[8];
        #pragma unroll
        for (int cc = 0; cc < 8; cc++) bias[cc] = bb[o0 + cc];
        #pragma unroll
        for (int rr = 0; rr < 8; rr++) {
            #pragma unroll
            for (int cp = 0; cp < 4; cp++) {
                float v0 = __uint_as_float((unsigned)(acc[rr][cp] & 0xffffffffull));
                float v1 = __uint_as_float((unsigned)(acc[rr][cp] >> 32));
                hA[(r0 + rr) * Hq + o0 + cp * 2]     = lrelu(v0 + bias[cp * 2]);
                hA[(r0 + rr) * Hq + o0 + cp * 2 + 1] = lrelu(v1 + bias[cp * 2 + 1]);
            }
        }
        __syncthreads();
    }

    // ---- Final layer: 64x256 @ 256x64 -> tokens (no activation) ----
    {
        const float* W = Wf + (size_t)i * Hq * Eq;
        const float* bb = bf + i * Eq;
        const int r0 = ty * 8, o0 = tx * 2;

        ull acc[8];
        #pragma unroll
        for (int rr = 0; rr < 8; rr++) acc[rr] = 0ull;

        for (int kb = 0; kb < Hq; kb += 32) {
            const float4* Wg = (const float4*)(W + (size_t)kb * Eq);
            float4* Ws4 = (float4*)Ws;
            #pragma unroll
            for (int j = 0; j < 2; j++) Ws4[tid + j * 256] = Wg[tid + j * 256];
            __syncthreads();

            #pragma unroll 8
            for (int kk = 0; kk < 32; kk++) {
                ull wv = *(const ull*)(Ws + kk * Eq + o0);
                #pragma unroll
                for (int rr = 0; rr < 8; rr++) {
                    unsigned av = __float_as_uint(hA[(r0 + rr) * Hq + kb + kk]);
                    ull ap;
                    asm("mov.b64 %0, {%1,%1};" : "=l"(ap) : "r"(av));
                    asm("fma.rn.f32x2 %0, %1, %2, %0;" : "+l"(acc[rr]) : "l"(ap), "l"(wv));
                }
            }
            __syncthreads();
        }

        float bv0 = bb[o0], bv1 = bb[o0 + 1];
        #pragma unroll
        for (int rr = 0; rr < 8; rr++) {
            float v0 = __uint_as_float((unsigned)(acc[rr] & 0xffffffffull)) + bv0;
            float v1 = __uint_as_float((unsigned)(acc[rr] >> 32)) + bv1;
            float2* dst = (float2*)&g_tokens[(size_t)(rb + r0 + rr) * (Dq * Eq) + i * Eq + o0];
            *dst = make_float2(v0, v1);
        }
    }
}

// ---------------------------------------------------------------------------
// Attention kernel: one warp per batch row. 8 warps/CTA.
// Per-warp SMEM: T(1088) Q(1088) K(1088) SC(1156) VG(68) = 4488 floats.
// ---------------------------------------------------------------------------
#define WARP_FLOATS 4488
#define SMEM_ATTN (8 * WARP_FLOATS * 4)

__global__ __launch_bounds__(256) void attn_kernel(
    const float* __restrict__ Wq, const float* __restrict__ bq,
    const float* __restrict__ Wk, const float* __restrict__ bk,
    const float* __restrict__ bfc, float* __restrict__ out) {
    extern __shared__ __align__(16) float smem[];
    const int lane = threadIdx.x & 31;
    const int w = threadIdx.x >> 5;
    const int b = blockIdx.x * 8 + w;

    float* T = smem + w * WARP_FLOATS;
    float* Q = T + Dq * Eq;
    float* K = Q + Dq * Eq;
    float* SC = K + Dq * Eq;
    float* VG = SC + NHq * Dq * Dq;

    const float* tok = g_tokens + (size_t)b * (Dq * Eq);
    for (int idx = lane; idx < Dq * Eq; idx += 32) T[idx] = tok[idx];
    __syncwarp();

    // vg[h,k] = T[k] . wvg[h] + bvg[h]
    for (int idx = lane; idx < NHq * Dq; idx += 32) {
        int h = idx / Dq, k = idx - h * Dq;
        const float4* Tk = (const float4*)(T + k * Eq);
        const float4* wv = (const float4*)(g_wvg + h * Eq);
        float s = g_bvg[h];
        #pragma unroll
        for (int f = 0; f < 16; f++) {
            float4 t4 = Tk[f], w4 = wv[f];
            s += t4.x * w4.x + t4.y * w4.y + t4.z * w4.z + t4.w * w4.w;
        }
        VG[idx] = s;
    }

    // Q, K projections (torch Linear: y = x @ W^T + b). Fold 1/sqrt(hd)=0.25 into Q.
    for (int idx = lane; idx < Dq * Eq; idx += 32) {
        int d = idx >> 6, e = idx & 63;
        const float4* Td = (const float4*)(T + (d << 6));
        const float4* wq = (const float4*)(Wq + (e << 6));
        const float4* wk = (const float4*)(Wk + (e << 6));
        float sq = bq[e], sk = bk[e];
        #pragma unroll
        for (int f = 0; f < 16; f++) {
            float4 t4 = Td[f], q4 = wq[f], k4 = wk[f];
            sq += t4.x * q4.x + t4.y * q4.y + t4.z * q4.z + t4.w * q4.w;
            sk += t4.x * k4.x + t4.y * k4.y + t4.z * k4.z + t4.w * k4.w;
        }
        Q[idx] = sq * 0.25f;
        K[idx] = sk;
    }
    __syncwarp();

    // scores[h][qd][kd]
    for (int idx = lane; idx < NHq * Dq * Dq; idx += 32) {
        int h = idx / (Dq * Dq);
        int rem = idx - h * (Dq * Dq);
        int qd = rem / Dq, kd = rem - qd * Dq;
        const float4* Qp = (const float4*)(Q + qd * Eq + h * 16);
        const float4* Kp = (const float4*)(K + kd * Eq + h * 16);
        float s = 0.f;
        #pragma unroll
        for (int c = 0; c < 4; c++) {
            float4 q4 = Qp[c], k4 = Kp[c];
            s += q4.x * k4.x + q4.y * k4.y + q4.z * k4.z + q4.w * k4.w;
        }
        SC[idx] = s;
    }
    __syncwarp();

    // softmax rows + weighted accumulate against vg
    float part = 0.f;
    for (int idx = lane; idx < NHq * Dq; idx += 32) {
        int h = idx / Dq, qd = idx - h * Dq;
        const float* row = SC + h * (Dq * Dq) + qd * Dq;
        const float* vg = VG + h * Dq;
        float m = row[0];
        #pragma unroll
        for (int k = 1; k < Dq; k++) m = fmaxf(m, row[k]);
        float se = 0.f, dot = 0.f;
        #pragma unroll
        for (int k = 0; k < Dq; k++) {
            float e = __expf(row[k] - m);
            se += e;
            dot += e * vg[k];
        }
        part += dot / se;
    }
    #pragma unroll
    for (int off = 16; off; off >>= 1) part += __shfl_down_sync(0xffffffffu, part, off);
    if (lane == 0) out[b] = lrelu(part * (1.f / 17.f) + g_c0[0] + bfc[0]);
}

// ---------------------------------------------------------------------------
extern "C" void kernel_launch(void* const* d_in, const int* in_sizes, int n_in,
                              void* d_out, int out_size) {
    (void)in_sizes; (void)n_in; (void)out_size;
    const float* x   = (const float*)d_in[0];
    const float* W1  = (const float*)d_in[1];
    const float* b1  = (const float*)d_in[2];
    const float* Wm  = (const float*)d_in[3];
    const float* bm  = (const float*)d_in[4];
    const float* Wf  = (const float*)d_in[5];
    const float* bf  = (const float*)d_in[6];
    const float* Wq  = (const float*)d_in[7];
    const float* bq  = (const float*)d_in[8];
    const float* Wk  = (const float*)d_in[9];
    const float* bk  = (const float*)d_in[10];
    const float* Wv  = (const float*)d_in[11];
    const float* bv  = (const float*)d_in[12];
    const float* Wo  = (const float*)d_in[13];
    const float* bo  = (const float*)d_in[14];
    const float* Wfc = (const float*)d_in[15];
    const float* bfc = (const float*)d_in[16];
    float* out = (float*)d_out;

    cudaFuncSetAttribute(subnet_kernel, cudaFuncAttributeMaxDynamicSharedMemorySize, SMEM_SUBNET);
    cudaFuncSetAttribute(attn_kernel, cudaFuncAttributeMaxDynamicSharedMemorySize, SMEM_ATTN);

    precompute_kernel<<<1, 256>>>(Wo, bo, Wfc, Wv, bv);
    subnet_kernel<<<dim3(Bq / TB, Dq), 256, SMEM_SUBNET>>>(x, W1, b1, Wm, bm, Wf, bf);
    attn_kernel<<<Bq / 8, 256, SMEM_ATTN>>>(Wq, bq, Wk, bk, bfc, out);
}

// round 6
// speedup vs baseline: 1.3503x; 1.3503x over previous
#include <cuda_runtime.h>
#include <cuda_bf16.h>
#include <cstdint>

#define Bq 16384
#define Dq 17
#define Hq 256
#define Eq 64
#define NHq 4
#define SLOPE 0.01f

// ---------------------------------------------------------------------------
// Device scratch
// ---------------------------------------------------------------------------
__device__ float g_tokens[(size_t)Bq * Dq * Eq];                   // 71.3 MB
__device__ __align__(16) float g_gvec[Eq];
__device__ __align__(16) float g_wvg[NHq * Eq];
__device__ float g_bvg[NHq];
__device__ float g_c0[1];
// bf16 hi/lo split weights, [k][n] row-major (natural Wm layout)
__device__ __align__(16) __nv_bfloat16 g_midHi[(size_t)34 * 65536];
__device__ __align__(16) __nv_bfloat16 g_midLo[(size_t)34 * 65536];
__device__ __align__(16) __nv_bfloat16 g_finHi[(size_t)17 * 16384];
__device__ __align__(16) __nv_bfloat16 g_finLo[(size_t)17 * 16384];

__device__ __forceinline__ float lrelu(float v) { return v >= 0.f ? v : SLOPE * v; }

// ---------------------------------------------------------------------------
// Baseline-PTX helpers (sm_80+: ldmatrix / mma.sync / cp.async)
// ---------------------------------------------------------------------------
__device__ __forceinline__ void ldsm4(uint32_t addr, uint32_t* r) {
    asm volatile("ldmatrix.sync.aligned.m8n8.x4.shared.b16 {%0,%1,%2,%3}, [%4];"
                 : "=r"(r[0]), "=r"(r[1]), "=r"(r[2]), "=r"(r[3]) : "r"(addr));
}
__device__ __forceinline__ void ldsm4t(uint32_t addr, uint32_t* r) {
    asm volatile("ldmatrix.sync.aligned.m8n8.x4.trans.shared.b16 {%0,%1,%2,%3}, [%4];"
                 : "=r"(r[0]), "=r"(r[1]), "=r"(r[2]), "=r"(r[3]) : "r"(addr));
}
__device__ __forceinline__ void mma_bf(float* d, const uint32_t* a, const uint32_t* b) {
    asm volatile("mma.sync.aligned.m16n8k16.row.col.f32.bf16.bf16.f32 "
                 "{%0,%1,%2,%3}, {%4,%5,%6,%7}, {%8,%9}, {%0,%1,%2,%3};"
                 : "+f"(d[0]), "+f"(d[1]), "+f"(d[2]), "+f"(d[3])
                 : "r"(a[0]), "r"(a[1]), "r"(a[2]), "r"(a[3]), "r"(b[0]), "r"(b[1]));
}
#define CP_A16(s, g) asm volatile("cp.async.ca.shared.global [%0], [%1], 16;" :: "r"(s), "l"(g))
#define CP_COMMIT()  asm volatile("cp.async.commit_group;")
#define CP_WAIT0()   asm volatile("cp.async.wait_group 0;" ::: "memory")

// SMEM layout (bytes)
#define SA_LO   67584          // hA_hi [128][264]bf16 = 67584
#define WB      135168         // hA_lo ends here
#define WBUF    33792          // per W buffer (hi+lo)
#define MIDLO   16896          // lo offset within mid buffer
#define FINLO   4608           // lo offset within fin buffer
#define SMEM_SUB 202752

extern __shared__ __align__(16) char dyn_smem[];

// ---------------------------------------------------------------------------
// Precompute folded epilogue weights
// ---------------------------------------------------------------------------
__global__ void precompute_kernel(const float* __restrict__ Wo, const float* __restrict__ bo,
                                  const float* __restrict__ Wfc, const float* __restrict__ Wv,
                                  const float* __restrict__ bv) {
    __shared__ float gs[Eq];
    int t = threadIdx.x;
    if (t < Eq) {
        float s = 0.f;
        for (int e = 0; e < Eq; e++) s += Wo[e * Eq + t] * Wfc[e];
        gs[t] = s;
        g_gvec[t] = s;
    }
    if (t == Eq) {
        float s = 0.f;
        for (int e = 0; e < Eq; e++) s += bo[e] * Wfc[e];
        g_c0[0] = s;
    }
    __syncthreads();
    {
        int h = t >> 6, f = t & 63;
        float s = 0.f;
        for (int c = 0; c < 16; c++) s += Wv[(h * 16 + c) * Eq + f] * gs[h * 16 + c];
        g_wvg[t] = s;
    }
    if (t < NHq) {
        float s = 0.f;
        for (int c = 0; c < 16; c++) s += bv[t * 16 + c] * gs[t * 16 + c];
        g_bvg[t] = s;
    }
}

// ---------------------------------------------------------------------------
// Pack: hi/lo bf16 split, natural [k][n] layout
// ---------------------------------------------------------------------------
__global__ void pack_mid_kernel(const float* __restrict__ Wm) {
    size_t idx = (size_t)blockIdx.x * 256 + threadIdx.x;   // li*65536 + k*256 + n
    float w = Wm[idx];
    __nv_bfloat16 h = __float2bfloat16(w);
    g_midHi[idx] = h;
    g_midLo[idx] = __float2bfloat16(w - __bfloat162float(h));
}
__global__ void pack_fin_kernel(const float* __restrict__ Wf) {
    size_t idx = (size_t)blockIdx.x * 64 + threadIdx.x;    // i*16384 + k*64 + n
    float w = Wf[idx];
    __nv_bfloat16 h = __float2bfloat16(w);
    g_finHi[idx] = h;
    g_finLo[idx] = __float2bfloat16(w - __bfloat162float(h));
}

// ---------------------------------------------------------------------------
// cp.async chunk loaders (all 256 threads)
// ---------------------------------------------------------------------------
__device__ __forceinline__ void issue_mid(uint32_t sb, int tid, int li, int c, int b) {
    const __nv_bfloat16* bh = g_midHi + (size_t)li * 65536 + (size_t)c * 8192;
    const __nv_bfloat16* bl = g_midLo + (size_t)li * 65536 + (size_t)c * 8192;
    #pragma unroll
    for (int j = 0; j < 8; ++j) {
        int lin = j * 256 + tid;
        int s = lin >> 10, rem = lin & 1023, row = rem >> 5, seg = rem & 31;
        const __nv_bfloat16* g = (s ? bl : bh) + row * 256 + seg * 8;
        uint32_t sa = sb + WB + (uint32_t)b * WBUF + (uint32_t)s * MIDLO +
                      (uint32_t)row * 528 + (uint32_t)seg * 16;
        CP_A16(sa, g);
    }
    CP_COMMIT();
}
__device__ __forceinline__ void issue_fin(uint32_t sb, int tid, int i, int c, int b) {
    const __nv_bfloat16* bh = g_finHi + (size_t)i * 16384 + (size_t)c * 2048;
    const __nv_bfloat16* bl = g_finLo + (size_t)i * 16384 + (size_t)c * 2048;
    #pragma unroll
    for (int j = 0; j < 2; ++j) {
        int lin = j * 256 + tid;
        int s = lin >> 8, rem = lin & 255, row = rem >> 3, seg = rem & 7;
        const __nv_bfloat16* g = (s ? bl : bh) + row * 64 + seg * 8;
        uint32_t sa = sb + WB + (uint32_t)b * WBUF + (uint32_t)s * FINLO +
                      (uint32_t)row * 144 + (uint32_t)seg * 16;
        CP_A16(sa, g);
    }
    CP_COMMIT();
}

// ---------------------------------------------------------------------------
// Subnet: grid (128, 17), 256 threads. hA hi/lo persistent in SMEM,
// mma.sync bf16x3, cp.async double-buffered weight chunks (K=32 each).
// ---------------------------------------------------------------------------
__global__ __launch_bounds__(256, 1)
void subnet_mma_kernel(const float* __restrict__ x, const float* __restrict__ W1,
                       const float* __restrict__ b1, const float* __restrict__ bm,
                       const float* __restrict__ bf) {
    char* smem = dyn_smem;
    const uint32_t sb = (uint32_t)__cvta_generic_to_shared(smem);
    const int i = blockIdx.y;
    const int rb = blockIdx.x * 128;
    const int tid = threadIdx.x, wid = tid >> 5, lane = tid & 31;
    const int qr = ((lane >> 3) & 1) * 8 + (lane & 7);
    const int qc = (lane >> 4) * 8;
    const uint32_t thA = (uint32_t)qr * 528 + (uint32_t)qc * 2;   // A & mid-W tiles
    const uint32_t thWf = (uint32_t)qr * 144 + (uint32_t)qc * 2;  // fin-W tiles
    const int r0 = (wid >> 2) * 64, n0 = (wid & 3) * 64;          // mid warp tile
    const int r0f = wid * 16;                                     // fin warp rows

    issue_mid(sb, tid, i, 0, 0);   // prefetch layer-0 chunk 0

    // ---- Layer 0: h = lrelu(x*W1 + b1), hi/lo split into SMEM ----
    {
        int r = tid >> 1, cb = (tid & 1) * 128;
        float xv = x[(size_t)(rb + r) * Dq + i];
        const float* w1 = W1 + i * Hq;
        const float* bb = b1 + i * Hq;
        char* rowp = smem + (size_t)r * 528 + (size_t)cb * 2;
        #pragma unroll 8
        for (int c = 0; c < 128; c += 2) {
            float v0 = lrelu(fmaf(xv, w1[cb + c], bb[cb + c]));
            float v1 = lrelu(fmaf(xv, w1[cb + c + 1], bb[cb + c + 1]));
            __nv_bfloat16 h0 = __float2bfloat16(v0), h1 = __float2bfloat16(v1);
            uint32_t hw = ((uint32_t)__bfloat16_as_ushort(h1) << 16) |
                          (uint32_t)__bfloat16_as_ushort(h0);
            __nv_bfloat16 e0 = __float2bfloat16(v0 - __bfloat162float(h0));
            __nv_bfloat16 e1 = __float2bfloat16(v1 - __bfloat162float(h1));
            uint32_t lw = ((uint32_t)__bfloat16_as_ushort(e1) << 16) |
                          (uint32_t)__bfloat16_as_ushort(e0);
            *(uint32_t*)(rowp + c * 2) = hw;
            *(uint32_t*)(rowp + SA_LO + c * 2) = lw;
        }
    }

    for (int l = 0; l < 3; ++l) {
        float acc[4][8][4];
        #pragma unroll
        for (int a = 0; a < 4; ++a)
            #pragma unroll
            for (int b = 0; b < 8; ++b)
                #pragma unroll
                for (int q = 0; q < 4; ++q) acc[a][b][q] = 0.f;

        for (int c = 0; c < 8; ++c) {
            CP_WAIT0();
            __syncthreads();
            if (c < 7) {
                if (l < 2) issue_mid(sb, tid, l * 17 + i, c + 1, (c + 1) & 1);
                else       issue_fin(sb, tid, i, c + 1, (c + 1) & 1);
            }
            const uint32_t wb = sb + WB + (uint32_t)(c & 1) * WBUF;

            if (l < 2) {
                #pragma unroll
                for (int ks = 0; ks < 2; ++ks) {
                    uint32_t ah[4][4], bh[4][4];
                    const uint32_t abase = sb + (uint32_t)r0 * 528 +
                                           (uint32_t)(c * 32 + ks * 16) * 2 + thA;
                    #pragma unroll
                    for (int mi = 0; mi < 4; ++mi) ldsm4(abase + mi * 8448, ah[mi]);
                    const uint32_t bbase = wb + (uint32_t)(ks * 16) * 528 +
                                           (uint32_t)n0 * 2 + thA;
                    #pragma unroll
                    for (int nj = 0; nj < 4; ++nj) ldsm4t(bbase + nj * 32, bh[nj]);
                    // pass 1: Ah * Bh
                    #pragma unroll
                    for (int mi = 0; mi < 4; ++mi)
                        #pragma unroll
                        for (int nj = 0; nj < 4; ++nj) {
                            mma_bf(acc[mi][2 * nj], ah[mi], bh[nj]);
                            mma_bf(acc[mi][2 * nj + 1], ah[mi], bh[nj] + 2);
                        }
                    // pass 2: Ah * Bl
                    #pragma unroll
                    for (int nj = 0; nj < 4; ++nj) {
                        uint32_t bl[4];
                        ldsm4t(bbase + MIDLO + nj * 32, bl);
                        #pragma unroll
                        for (int mi = 0; mi < 4; ++mi) {
                            mma_bf(acc[mi][2 * nj], ah[mi], bl);
                            mma_bf(acc[mi][2 * nj + 1], ah[mi], bl + 2);
                        }
                    }
                    // pass 3: Al * Bh
                    #pragma unroll
                    for (int mi = 0; mi < 4; ++mi) {
                        uint32_t al[4];
                        ldsm4(abase + SA_LO + mi * 8448, al);
                        #pragma unroll
                        for (int nj = 0; nj < 4; ++nj) {
                            mma_bf(acc[mi][2 * nj], al, bh[nj]);
                            mma_bf(acc[mi][2 * nj + 1], al, bh[nj] + 2);
                        }
                    }
                }
            } else {
                #pragma unroll
                for (int ks = 0; ks < 2; ++ks) {
                    uint32_t ah[4], al[4], bh[4][4];
                    const uint32_t abase = sb + (uint32_t)r0f * 528 +
                                           (uint32_t)(c * 32 + ks * 16) * 2 + thA;
                    ldsm4(abase, ah);
                    ldsm4(abase + SA_LO, al);
                    const uint32_t bbase = wb + (uint32_t)(ks * 16) * 144 + thWf;
                    #pragma unroll
                    for (int nj = 0; nj < 4; ++nj) ldsm4t(bbase + nj * 32, bh[nj]);
                    #pragma unroll
                    for (int nj = 0; nj < 4; ++nj) {
                        mma_bf(acc[0][2 * nj], ah, bh[nj]);
                        mma_bf(acc[0][2 * nj + 1], ah, bh[nj] + 2);
                        mma_bf(acc[0][2 * nj], al, bh[nj]);
                        mma_bf(acc[0][2 * nj + 1], al, bh[nj] + 2);
                        uint32_t bl[4];
                        ldsm4t(bbase + FINLO + nj * 32, bl);
                        mma_bf(acc[0][2 * nj], ah, bl);
                        mma_bf(acc[0][2 * nj + 1], ah, bl + 2);
                    }
                }
            }
            __syncthreads();
        }

        if (l < 2) {
            if (l == 0) issue_mid(sb, tid, 17 + i, 0, 0);
            else        issue_fin(sb, tid, i, 0, 0);
            // epilogue: acc + bias -> lrelu -> hi/lo -> hA
            const float* bmL = bm + (size_t)(l * 17 + i) * 256;
            const int erow = lane >> 2, ecol = (lane & 3) * 2;
            #pragma unroll
            for (int mi = 0; mi < 4; ++mi)
                #pragma unroll
                for (int ni = 0; ni < 8; ++ni) {
                    int col = n0 + ni * 8 + ecol;
                    float b0v = bmL[col], b1v = bmL[col + 1];
                    #pragma unroll
                    for (int half = 0; half < 2; ++half) {
                        int row = r0 + mi * 16 + erow + half * 8;
                        float v0 = lrelu(acc[mi][ni][half * 2] + b0v);
                        float v1 = lrelu(acc[mi][ni][half * 2 + 1] + b1v);
                        __nv_bfloat16 h0 = __float2bfloat16(v0), h1 = __float2bfloat16(v1);
                        uint32_t hw = ((uint32_t)__bfloat16_as_ushort(h1) << 16) |
                                      (uint32_t)__bfloat16_as_ushort(h0);
                        __nv_bfloat16 e0 = __float2bfloat16(v0 - __bfloat162float(h0));
                        __nv_bfloat16 e1 = __float2bfloat16(v1 - __bfloat162float(h1));
                        uint32_t lw = ((uint32_t)__bfloat16_as_ushort(e1) << 16) |
                                      (uint32_t)__bfloat16_as_ushort(e0);
                        char* p = smem + (size_t)row * 528 + (size_t)col * 2;
                        *(uint32_t*)p = hw;
                        *(uint32_t*)(p + SA_LO) = lw;
                    }
                }
            __syncthreads();
        } else {
            const float* bfL = bf + i * Eq;
            const int erow = lane >> 2, ecol = (lane & 3) * 2;
            #pragma unroll
            for (int ni = 0; ni < 8; ++ni) {
                int col = ni * 8 + ecol;
                float b0v = bfL[col], b1v = bfL[col + 1];
                int row = r0f + erow;
                float2 v0 = make_float2(acc[0][ni][0] + b0v, acc[0][ni][1] + b1v);
                float2 v1 = make_float2(acc[0][ni][2] + b0v, acc[0][ni][3] + b1v);
                *(float2*)&g_tokens[(size_t)(rb + row) * (Dq * Eq) + i * Eq + col] = v0;
                *(float2*)&g_tokens[(size_t)(rb + row + 8) * (Dq * Eq) + i * Eq + col] = v1;
            }
        }
    }
}

// ---------------------------------------------------------------------------
// Attention: one warp per batch row, 8 warps/CTA (unchanged from R1-pass).
// ---------------------------------------------------------------------------
#define WARP_FLOATS 4488
#define SMEM_ATTN (8 * WARP_FLOATS * 4)

__global__ __launch_bounds__(256) void attn_kernel(
    const float* __restrict__ Wq, const float* __restrict__ bq,
    const float* __restrict__ Wk, const float* __restrict__ bk,
    const float* __restrict__ bfc, float* __restrict__ out) {
    float* smem = (float*)dyn_smem;
    const int lane = threadIdx.x & 31;
    const int w = threadIdx.x >> 5;
    const int b = blockIdx.x * 8 + w;

    float* T = smem + w * WARP_FLOATS;
    float* Q = T + Dq * Eq;
    float* K = Q + Dq * Eq;
    float* SC = K + Dq * Eq;
    float* VG = SC + NHq * Dq * Dq;

    const float* tok = g_tokens + (size_t)b * (Dq * Eq);
    for (int idx = lane; idx < Dq * Eq; idx += 32) T[idx] = tok[idx];
    __syncwarp();

    for (int idx = lane; idx < NHq * Dq; idx += 32) {
        int h = idx / Dq, k = idx - h * Dq;
        const float4* Tk = (const float4*)(T + k * Eq);
        const float4* wv = (const float4*)(g_wvg + h * Eq);
        float s = g_bvg[h];
        #pragma unroll
        for (int f = 0; f < 16; f++) {
            float4 t4 = Tk[f], w4 = wv[f];
            s += t4.x * w4.x + t4.y * w4.y + t4.z * w4.z + t4.w * w4.w;
        }
        VG[idx] = s;
    }

    for (int idx = lane; idx < Dq * Eq; idx += 32) {
        int d = idx >> 6, e = idx & 63;
        const float4* Td = (const float4*)(T + (d << 6));
        const float4* wq = (const float4*)(Wq + (e << 6));
        const float4* wk = (const float4*)(Wk + (e << 6));
        float sq = bq[e], sk = bk[e];
        #pragma unroll
        for (int f = 0; f < 16; f++) {
            float4 t4 = Td[f], q4 = wq[f], k4 = wk[f];
            sq += t4.x * q4.x + t4.y * q4.y + t4.z * q4.z + t4.w * q4.w;
            sk += t4.x * k4.x + t4.y * k4.y + t4.z * k4.z + t4.w * k4.w;
        }
        Q[idx] = sq * 0.25f;
        K[idx] = sk;
    }
    __syncwarp();

    for (int idx = lane; idx < NHq * Dq * Dq; idx += 32) {
        int h = idx / (Dq * Dq);
        int rem = idx - h * (Dq * Dq);
        int qd = rem / Dq, kd = rem - qd * Dq;
        const float4* Qp = (const float4*)(Q + qd * Eq + h * 16);
        const float4* Kp = (const float4*)(K + kd * Eq + h * 16);
        float s = 0.f;
        #pragma unroll
        for (int c = 0; c < 4; c++) {
            float4 q4 = Qp[c], k4 = Kp[c];
            s += q4.x * k4.x + q4.y * k4.y + q4.z * k4.z + q4.w * k4.w;
        }
        SC[idx] = s;
    }
    __syncwarp();

    float part = 0.f;
    for (int idx = lane; idx < NHq * Dq; idx += 32) {
        int h = idx / Dq, qd = idx - h * Dq;
        const float* row = SC + h * (Dq * Dq) + qd * Dq;
        const float* vg = VG + h * Dq;
        float m = row[0];
        #pragma unroll
        for (int k = 1; k < Dq; k++) m = fmaxf(m, row[k]);
        float se = 0.f, dot = 0.f;
        #pragma unroll
        for (int k = 0; k < Dq; k++) {
            float e = __expf(row[k] - m);
            se += e;
            dot += e * vg[k];
        }
        part += dot / se;
    }
    #pragma unroll
    for (int off = 16; off; off >>= 1) part += __shfl_down_sync(0xffffffffu, part, off);
    if (lane == 0) out[b] = lrelu(part * (1.f / 17.f) + g_c0[0] + bfc[0]);
}

// ---------------------------------------------------------------------------
extern "C" void kernel_launch(void* const* d_in, const int* in_sizes, int n_in,
                              void* d_out, int out_size) {
    (void)in_sizes; (void)n_in; (void)out_size;
    const float* x   = (const float*)d_in[0];
    const float* W1  = (const float*)d_in[1];
    const float* b1  = (const float*)d_in[2];
    const float* Wm  = (const float*)d_in[3];
    const float* bm  = (const float*)d_in[4];
    const float* Wf  = (const float*)d_in[5];
    const float* bf  = (const float*)d_in[6];
    const float* Wq  = (const float*)d_in[7];
    const float* bq  = (const float*)d_in[8];
    const float* Wk  = (const float*)d_in[9];
    const float* bk  = (const float*)d_in[10];
    const float* Wv  = (const float*)d_in[11];
    const float* bv  = (const float*)d_in[12];
    const float* Wo  = (const float*)d_in[13];
    const float* bo  = (const float*)d_in[14];
    const float* Wfc = (const float*)d_in[15];
    const float* bfc = (const float*)d_in[16];
    float* out = (float*)d_out;

    cudaFuncSetAttribute(subnet_mma_kernel, cudaFuncAttributeMaxDynamicSharedMemorySize, SMEM_SUB);
    cudaFuncSetAttribute(attn_kernel, cudaFuncAttributeMaxDynamicSharedMemorySize, SMEM_ATTN);

    precompute_kernel<<<1, 256>>>(Wo, bo, Wfc, Wv, bv);
    pack_mid_kernel<<<34 * 256, 256>>>(Wm);
    pack_fin_kernel<<<17 * 256, 64>>>(Wf);
    subnet_mma_kernel<<<dim3(Bq / 128, Dq), 256, SMEM_SUB>>>(x, W1, b1, bm, bf);
    attn_kernel<<<Bq / 8, 256, SMEM_ATTN>>>(Wq, bq, Wk, bk, bfc, out);
}

// round 7
// speedup vs baseline: 4.2033x; 3.1128x over previous
#include <cuda_runtime.h>
#include <cuda_bf16.h>
#include <cstdint>

#define Bq 16384
#define Dq 17
#define Hq 256
#define Eq 64
#define NHq 4
#define SLOPE 0.01f

// ---------------------------------------------------------------------------
// Device scratch
// ---------------------------------------------------------------------------
__device__ float g_qk[(size_t)Bq * Dq * 128];                      // 142.6 MB: Q(scaled)|K
__device__ float g_vg[(size_t)Bq * NHq * Dq];                      // 4.5 MB
__device__ __align__(16) float g_wvg[NHq * Eq];
__device__ float g_bvg[NHq];
__device__ float g_c0[1];
// bf16 hi/lo split weights, [k][n] row-major
__device__ __align__(16) __nv_bfloat16 g_midHi[(size_t)34 * 65536];
__device__ __align__(16) __nv_bfloat16 g_midLo[(size_t)34 * 65536];
__device__ __align__(16) __nv_bfloat16 g_finHi[(size_t)17 * 16384];
__device__ __align__(16) __nv_bfloat16 g_finLo[(size_t)17 * 16384];
// WqkT packed: [c 0..63][n 0..135] (n<64: Wq^T, 64..127: Wk^T, pad 128..135)
__device__ __align__(16) __nv_bfloat16 g_qkHi[64 * 136];
__device__ __align__(16) __nv_bfloat16 g_qkLo[64 * 136];

__device__ __forceinline__ float lrelu(float v) { return v >= 0.f ? v : SLOPE * v; }

// ---------------------------------------------------------------------------
// mma / ldmatrix / cp.async helpers (baseline PTX, sm_80+)
// ---------------------------------------------------------------------------
__device__ __forceinline__ void ldsm4(uint32_t addr, uint32_t* r) {
    asm volatile("ldmatrix.sync.aligned.m8n8.x4.shared.b16 {%0,%1,%2,%3}, [%4];"
                 : "=r"(r[0]), "=r"(r[1]), "=r"(r[2]), "=r"(r[3]) : "r"(addr));
}
__device__ __forceinline__ void ldsm4t(uint32_t addr, uint32_t* r) {
    asm volatile("ldmatrix.sync.aligned.m8n8.x4.trans.shared.b16 {%0,%1,%2,%3}, [%4];"
                 : "=r"(r[0]), "=r"(r[1]), "=r"(r[2]), "=r"(r[3]) : "r"(addr));
}
__device__ __forceinline__ void mma_bf(float* d, const uint32_t* a, const uint32_t* b) {
    asm volatile("mma.sync.aligned.m16n8k16.row.col.f32.bf16.bf16.f32 "
                 "{%0,%1,%2,%3}, {%4,%5,%6,%7}, {%8,%9}, {%0,%1,%2,%3};"
                 : "+f"(d[0]), "+f"(d[1]), "+f"(d[2]), "+f"(d[3])
                 : "r"(a[0]), "r"(a[1]), "r"(a[2]), "r"(a[3]), "r"(b[0]), "r"(b[1]));
}
#define CP_A16(s, g) asm volatile("cp.async.ca.shared.global [%0], [%1], 16;" :: "r"(s), "l"(g))
#define CP_COMMIT()  asm volatile("cp.async.commit_group;")
#define CP_WAIT0()   asm volatile("cp.async.wait_group 0;" ::: "memory")

// SMEM layout (bytes)
#define SA_LO   67584          // hA_hi [128][264]bf16
#define WB      135168         // hA_lo ends here; W buffers start
#define WBUF    33792
#define MIDLO   16896
#define FINLO   4608
#define QKHI    (WB + 9216)            // gap in fin buffer 0
#define QKLO    (WB + WBUF + 9216)     // gap in fin buffer 1
#define SMEM_SUB 202752

extern __shared__ __align__(16) char dyn_smem[];

// ---------------------------------------------------------------------------
// Precompute folded epilogue weights (g = Wo^T Wfc; wvg, bvg, c0)
// ---------------------------------------------------------------------------
__global__ void precompute_kernel(const float* __restrict__ Wo, const float* __restrict__ bo,
                                  const float* __restrict__ Wfc, const float* __restrict__ Wv,
                                  const float* __restrict__ bv) {
    __shared__ float gs[Eq];
    int t = threadIdx.x;
    if (t < Eq) {
        float s = 0.f;
        for (int e = 0; e < Eq; e++) s += Wo[e * Eq + t] * Wfc[e];
        gs[t] = s;
    }
    if (t == Eq) {
        float s = 0.f;
        for (int e = 0; e < Eq; e++) s += bo[e] * Wfc[e];
        g_c0[0] = s;
    }
    __syncthreads();
    {
        int h = t >> 6, f = t & 63;
        float s = 0.f;
        for (int c = 0; c < 16; c++) s += Wv[(h * 16 + c) * Eq + f] * gs[h * 16 + c];
        g_wvg[t] = s;
    }
    if (t < NHq) {
        float s = 0.f;
        for (int c = 0; c < 16; c++) s += bv[t * 16 + c] * gs[t * 16 + c];
        g_bvg[t] = s;
    }
}

// ---------------------------------------------------------------------------
// Pack kernels: hi/lo bf16 splits
// ---------------------------------------------------------------------------
__global__ void pack_mid_kernel(const float* __restrict__ Wm) {
    size_t idx = (size_t)blockIdx.x * 256 + threadIdx.x;
    float w = Wm[idx];
    __nv_bfloat16 h = __float2bfloat16(w);
    g_midHi[idx] = h;
    g_midLo[idx] = __float2bfloat16(w - __bfloat162float(h));
}
__global__ void pack_fin_kernel(const float* __restrict__ Wf) {
    size_t idx = (size_t)blockIdx.x * 64 + threadIdx.x;
    float w = Wf[idx];
    __nv_bfloat16 h = __float2bfloat16(w);
    g_finHi[idx] = h;
    g_finLo[idx] = __float2bfloat16(w - __bfloat162float(h));
}
__global__ void pack_qk_kernel(const float* __restrict__ Wq, const float* __restrict__ Wk) {
    int idx = blockIdx.x * 256 + threadIdx.x;   // 64*136 = 8704
    if (idx >= 64 * 136) return;
    int c = idx / 136, n = idx % 136;
    float w = 0.f;
    if (n < 64) w = Wq[n * Eq + c];
    else if (n < 128) w = Wk[(n - 64) * Eq + c];
    __nv_bfloat16 h = __float2bfloat16(w);
    g_qkHi[idx] = h;
    g_qkLo[idx] = __float2bfloat16(w - __bfloat162float(h));
}

// ---------------------------------------------------------------------------
// cp.async loaders
// ---------------------------------------------------------------------------
__device__ __forceinline__ void issue_mid(uint32_t sb, int tid, int li, int c, int b) {
    const __nv_bfloat16* bh = g_midHi + (size_t)li * 65536 + (size_t)c * 8192;
    const __nv_bfloat16* bl = g_midLo + (size_t)li * 65536 + (size_t)c * 8192;
    #pragma unroll
    for (int j = 0; j < 8; ++j) {
        int lin = j * 256 + tid;
        int s = lin >> 10, rem = lin & 1023, row = rem >> 5, seg = rem & 31;
        const __nv_bfloat16* g = (s ? bl : bh) + row * 256 + seg * 8;
        uint32_t sa = sb + WB + (uint32_t)b * WBUF + (uint32_t)s * MIDLO +
                      (uint32_t)row * 528 + (uint32_t)seg * 16;
        CP_A16(sa, g);
    }
    CP_COMMIT();
}
__device__ __forceinline__ void issue_fin(uint32_t sb, int tid, int i, int c, int b) {
    const __nv_bfloat16* bh = g_finHi + (size_t)i * 16384 + (size_t)c * 2048;
    const __nv_bfloat16* bl = g_finLo + (size_t)i * 16384 + (size_t)c * 2048;
    #pragma unroll
    for (int j = 0; j < 2; ++j) {
        int lin = j * 256 + tid;
        int s = lin >> 8, rem = lin & 255, row = rem >> 3, seg = rem & 7;
        const __nv_bfloat16* g = (s ? bl : bh) + row * 64 + seg * 8;
        uint32_t sa = sb + WB + (uint32_t)b * WBUF + (uint32_t)s * FINLO +
                      (uint32_t)row * 144 + (uint32_t)seg * 16;
        CP_A16(sa, g);
    }
    CP_COMMIT();
}
__device__ __forceinline__ void issue_qk(uint32_t sb, int tid) {
    #pragma unroll
    for (int j = 0; j < 9; ++j) {
        int lin = j * 256 + tid;
        if (lin < 2176) {
            int s = lin >= 1088;
            int rem = s ? lin - 1088 : lin;
            int row = rem / 17, seg = rem % 17;
            const __nv_bfloat16* g = (s ? g_qkLo : g_qkHi) + row * 136 + seg * 8;
            uint32_t sa = sb + (uint32_t)(s ? QKLO : QKHI) +
                          (uint32_t)row * 272 + (uint32_t)seg * 16;
            CP_A16(sa, g);
        }
    }
    CP_COMMIT();
}

// ---------------------------------------------------------------------------
// Subnet: grid (128, 17), 256 threads. Layers 0..2 + fused QK projection.
// ---------------------------------------------------------------------------
__global__ __launch_bounds__(256, 1)
void subnet_mma_kernel(const float* __restrict__ x, const float* __restrict__ W1,
                       const float* __restrict__ b1, const float* __restrict__ bm,
                       const float* __restrict__ bf, const float* __restrict__ bq,
                       const float* __restrict__ bk) {
    char* smem = dyn_smem;
    const uint32_t sb = (uint32_t)__cvta_generic_to_shared(smem);
    const int i = blockIdx.y;
    const int rb = blockIdx.x * 128;
    const int tid = threadIdx.x, wid = tid >> 5, lane = tid & 31;
    const int qr = ((lane >> 3) & 1) * 8 + (lane & 7);
    const int qc = (lane >> 4) * 8;
    const uint32_t thA = (uint32_t)qr * 528 + (uint32_t)qc * 2;
    const uint32_t thWf = (uint32_t)qr * 144 + (uint32_t)qc * 2;
    const uint32_t thQK = (uint32_t)qr * 272 + (uint32_t)qc * 2;
    const int r0 = (wid >> 2) * 64, n0 = (wid & 3) * 64;
    const int r0f = wid * 16;
    const int erow = lane >> 2, ecol = (lane & 3) * 2;

    issue_mid(sb, tid, i, 0, 0);

    // ---- Layer 0 ----
    {
        int r = tid >> 1, cb = (tid & 1) * 128;
        float xv = x[(size_t)(rb + r) * Dq + i];
        const float* w1 = W1 + i * Hq;
        const float* bb = b1 + i * Hq;
        char* rowp = smem + (size_t)r * 528 + (size_t)cb * 2;
        #pragma unroll 8
        for (int c = 0; c < 128; c += 2) {
            float v0 = lrelu(fmaf(xv, w1[cb + c], bb[cb + c]));
            float v1 = lrelu(fmaf(xv, w1[cb + c + 1], bb[cb + c + 1]));
            __nv_bfloat16 h0 = __float2bfloat16(v0), h1 = __float2bfloat16(v1);
            uint32_t hw = ((uint32_t)__bfloat16_as_ushort(h1) << 16) |
                          (uint32_t)__bfloat16_as_ushort(h0);
            __nv_bfloat16 e0 = __float2bfloat16(v0 - __bfloat162float(h0));
            __nv_bfloat16 e1 = __float2bfloat16(v1 - __bfloat162float(h1));
            uint32_t lw = ((uint32_t)__bfloat16_as_ushort(e1) << 16) |
                          (uint32_t)__bfloat16_as_ushort(e0);
            *(uint32_t*)(rowp + c * 2) = hw;
            *(uint32_t*)(rowp + SA_LO + c * 2) = lw;
        }
    }

    for (int l = 0; l < 3; ++l) {
        float acc[4][8][4];
        #pragma unroll
        for (int a = 0; a < 4; ++a)
            #pragma unroll
            for (int b = 0; b < 8; ++b)
                #pragma unroll
                for (int q = 0; q < 4; ++q) acc[a][b][q] = 0.f;

        for (int c = 0; c < 8; ++c) {
            CP_WAIT0();
            __syncthreads();
            if (c < 7) {
                if (l < 2) issue_mid(sb, tid, l * 17 + i, c + 1, (c + 1) & 1);
                else       issue_fin(sb, tid, i, c + 1, (c + 1) & 1);
            }
            const uint32_t wb = sb + WB + (uint32_t)(c & 1) * WBUF;

            if (l < 2) {
                #pragma unroll
                for (int ks = 0; ks < 2; ++ks) {
                    uint32_t ah[4][4], bh[4][4];
                    const uint32_t abase = sb + (uint32_t)r0 * 528 +
                                           (uint32_t)(c * 32 + ks * 16) * 2 + thA;
                    #pragma unroll
                    for (int mi = 0; mi < 4; ++mi) ldsm4(abase + mi * 8448, ah[mi]);
                    const uint32_t bbase = wb + (uint32_t)(ks * 16) * 528 +
                                           (uint32_t)n0 * 2 + thA;
                    #pragma unroll
                    for (int nj = 0; nj < 4; ++nj) ldsm4t(bbase + nj * 32, bh[nj]);
                    #pragma unroll
                    for (int mi = 0; mi < 4; ++mi)
                        #pragma unroll
                        for (int nj = 0; nj < 4; ++nj) {
                            mma_bf(acc[mi][2 * nj], ah[mi], bh[nj]);
                            mma_bf(acc[mi][2 * nj + 1], ah[mi], bh[nj] + 2);
                        }
                    #pragma unroll
                    for (int nj = 0; nj < 4; ++nj) {
                        uint32_t bl[4];
                        ldsm4t(bbase + MIDLO + nj * 32, bl);
                        #pragma unroll
                        for (int mi = 0; mi < 4; ++mi) {
                            mma_bf(acc[mi][2 * nj], ah[mi], bl);
                            mma_bf(acc[mi][2 * nj + 1], ah[mi], bl + 2);
                        }
                    }
                    #pragma unroll
                    for (int mi = 0; mi < 4; ++mi) {
                        uint32_t al[4];
                        ldsm4(abase + SA_LO + mi * 8448, al);
                        #pragma unroll
                        for (int nj = 0; nj < 4; ++nj) {
                            mma_bf(acc[mi][2 * nj], al, bh[nj]);
                            mma_bf(acc[mi][2 * nj + 1], al, bh[nj] + 2);
                        }
                    }
                }
            } else {
                #pragma unroll
                for (int ks = 0; ks < 2; ++ks) {
                    uint32_t ah[4], al[4], bh[4][4];
                    const uint32_t abase = sb + (uint32_t)r0f * 528 +
                                           (uint32_t)(c * 32 + ks * 16) * 2 + thA;
                    ldsm4(abase, ah);
                    ldsm4(abase + SA_LO, al);
                    const uint32_t bbase = wb + (uint32_t)(ks * 16) * 144 + thWf;
                    #pragma unroll
                    for (int nj = 0; nj < 4; ++nj) ldsm4t(bbase + nj * 32, bh[nj]);
                    #pragma unroll
                    for (int nj = 0; nj < 4; ++nj) {
                        mma_bf(acc[0][2 * nj], ah, bh[nj]);
                        mma_bf(acc[0][2 * nj + 1], ah, bh[nj] + 2);
                        mma_bf(acc[0][2 * nj], al, bh[nj]);
                        mma_bf(acc[0][2 * nj + 1], al, bh[nj] + 2);
                        uint32_t bl[4];
                        ldsm4t(bbase + FINLO + nj * 32, bl);
                        mma_bf(acc[0][2 * nj], ah, bl);
                        mma_bf(acc[0][2 * nj + 1], ah, bl + 2);
                    }
                }
            }
            __syncthreads();
        }

        if (l < 2) {
            if (l == 0) {
                issue_mid(sb, tid, 17 + i, 0, 0);
            } else {
                issue_fin(sb, tid, i, 0, 0);
                issue_qk(sb, tid);
            }
            const float* bmL = bm + (size_t)(l * 17 + i) * 256;
            #pragma unroll
            for (int mi = 0; mi < 4; ++mi)
                #pragma unroll
                for (int ni = 0; ni < 8; ++ni) {
                    int col = n0 + ni * 8 + ecol;
                    float b0v = bmL[col], b1v = bmL[col + 1];
                    #pragma unroll
                    for (int half = 0; half < 2; ++half) {
                        int row = r0 + mi * 16 + erow + half * 8;
                        float v0 = lrelu(acc[mi][ni][half * 2] + b0v);
                        float v1 = lrelu(acc[mi][ni][half * 2 + 1] + b1v);
                        __nv_bfloat16 h0 = __float2bfloat16(v0), h1 = __float2bfloat16(v1);
                        uint32_t hw = ((uint32_t)__bfloat16_as_ushort(h1) << 16) |
                                      (uint32_t)__bfloat16_as_ushort(h0);
                        __nv_bfloat16 e0 = __float2bfloat16(v0 - __bfloat162float(h0));
                        __nv_bfloat16 e1 = __float2bfloat16(v1 - __bfloat162float(h1));
                        uint32_t lw = ((uint32_t)__bfloat16_as_ushort(e1) << 16) |
                                      (uint32_t)__bfloat16_as_ushort(e0);
                        char* p = smem + (size_t)row * 528 + (size_t)col * 2;
                        *(uint32_t*)p = hw;
                        *(uint32_t*)(p + SA_LO) = lw;
                    }
                }
            __syncthreads();
        } else {
            // ---- fin epilogue: + bias; vg via 4-lane reduce; tokens -> SMEM bf16 ----
            const float* bfL = bf + i * Eq;
            float pvg[2][NHq];
            #pragma unroll
            for (int h = 0; h < NHq; ++h) { pvg[0][h] = 0.f; pvg[1][h] = 0.f; }
            #pragma unroll
            for (int ni = 0; ni < 8; ++ni) {
                int col = ni * 8 + ecol;
                float b0v = bfL[col], b1v = bfL[col + 1];
                acc[0][ni][0] += b0v; acc[0][ni][1] += b1v;
                acc[0][ni][2] += b0v; acc[0][ni][3] += b1v;
                #pragma unroll
                for (int h = 0; h < NHq; ++h) {
                    float w0 = g_wvg[h * Eq + col], w1 = g_wvg[h * Eq + col + 1];
                    pvg[0][h] += acc[0][ni][0] * w0 + acc[0][ni][1] * w1;
                    pvg[1][h] += acc[0][ni][2] * w0 + acc[0][ni][3] * w1;
                }
            }
            #pragma unroll
            for (int h = 0; h < NHq; ++h) {
                #pragma unroll
                for (int off = 1; off < 4; off <<= 1) {
                    pvg[0][h] += __shfl_xor_sync(0xffffffffu, pvg[0][h], off);
                    pvg[1][h] += __shfl_xor_sync(0xffffffffu, pvg[1][h], off);
                }
            }
            {
                int h = lane & 3;
                float bvgh = g_bvg[h];
                size_t base0 = ((size_t)(rb + r0f + erow) * NHq + h) * Dq + i;
                size_t base1 = ((size_t)(rb + r0f + erow + 8) * NHq + h) * Dq + i;
                g_vg[base0] = pvg[0][h] + bvgh;
                g_vg[base1] = pvg[1][h] + bvgh;
            }
            // tokens (fp32 w/ bias) -> bf16 hi/lo into A region cols 0..63
            #pragma unroll
            for (int ni = 0; ni < 8; ++ni) {
                int col = ni * 8 + ecol;
                #pragma unroll
                for (int half = 0; half < 2; ++half) {
                    int row = r0f + erow + half * 8;
                    float v0 = acc[0][ni][half * 2];
                    float v1 = acc[0][ni][half * 2 + 1];
                    __nv_bfloat16 h0 = __float2bfloat16(v0), h1 = __float2bfloat16(v1);
                    uint32_t hw = ((uint32_t)__bfloat16_as_ushort(h1) << 16) |
                                  (uint32_t)__bfloat16_as_ushort(h0);
                    __nv_bfloat16 e0 = __float2bfloat16(v0 - __bfloat162float(h0));
                    __nv_bfloat16 e1 = __float2bfloat16(v1 - __bfloat162float(h1));
                    uint32_t lw = ((uint32_t)__bfloat16_as_ushort(e1) << 16) |
                                  (uint32_t)__bfloat16_as_ushort(e0);
                    char* p = smem + (size_t)row * 528 + (size_t)col * 2;
                    *(uint32_t*)p = hw;
                    *(uint32_t*)(p + SA_LO) = lw;
                }
            }
            __syncthreads();
        }
    }

    // ---- QK projection GEMM: [128x64] @ [64x128], bf16x3 ----
    {
        const int r0p = (wid >> 2) * 64, n0p = (wid & 3) * 32;
        float acc2[4][4][4];
        #pragma unroll
        for (int a = 0; a < 4; ++a)
            #pragma unroll
            for (int b = 0; b < 4; ++b)
                #pragma unroll
                for (int q = 0; q < 4; ++q) acc2[a][b][q] = 0.f;

        #pragma unroll
        for (int ks = 0; ks < 4; ++ks) {
            uint32_t ah[4][4], bh[2][4];
            const uint32_t abase = sb + (uint32_t)r0p * 528 + (uint32_t)(ks * 16) * 2 + thA;
            #pragma unroll
            for (int mi = 0; mi < 4; ++mi) ldsm4(abase + mi * 8448, ah[mi]);
            const uint32_t bbase = sb + QKHI + (uint32_t)(ks * 16) * 272 +
                                   (uint32_t)n0p * 2 + thQK;
            #pragma unroll
            for (int nj = 0; nj < 2; ++nj) ldsm4t(bbase + nj * 32, bh[nj]);
            #pragma unroll
            for (int mi = 0; mi < 4; ++mi)
                #pragma unroll
                for (int nj = 0; nj < 2; ++nj) {
                    mma_bf(acc2[mi][2 * nj], ah[mi], bh[nj]);
                    mma_bf(acc2[mi][2 * nj + 1], ah[mi], bh[nj] + 2);
                }
            #pragma unroll
            for (int nj = 0; nj < 2; ++nj) {
                uint32_t bl[4];
                ldsm4t(bbase + (QKLO - QKHI) + nj * 32, bl);
                #pragma unroll
                for (int mi = 0; mi < 4; ++mi) {
                    mma_bf(acc2[mi][2 * nj], ah[mi], bl);
                    mma_bf(acc2[mi][2 * nj + 1], ah[mi], bl + 2);
                }
            }
            #pragma unroll
            for (int mi = 0; mi < 4; ++mi) {
                uint32_t al[4];
                ldsm4(abase + SA_LO + mi * 8448, al);
                #pragma unroll
                for (int nj = 0; nj < 2; ++nj) {
                    mma_bf(acc2[mi][2 * nj], al, bh[nj]);
                    mma_bf(acc2[mi][2 * nj + 1], al, bh[nj] + 2);
                }
            }
        }
        // epilogue: Q=(v+bq)*0.25 (cols<64), K=v+bk
        #pragma unroll
        for (int mi = 0; mi < 4; ++mi)
            #pragma unroll
            for (int ni = 0; ni < 4; ++ni) {
                int col = n0p + ni * 8 + ecol;
                float bb0, bb1, sc;
                if (col < 64) { bb0 = bq[col]; bb1 = bq[col + 1]; sc = 0.25f; }
                else          { bb0 = bk[col - 64]; bb1 = bk[col - 63]; sc = 1.f; }
                #pragma unroll
                for (int half = 0; half < 2; ++half) {
                    int row = r0p + mi * 16 + erow + half * 8;
                    float v0 = (acc2[mi][ni][half * 2] + bb0) * sc;
                    float v1 = (acc2[mi][ni][half * 2 + 1] + bb1) * sc;
                    size_t o = ((size_t)(rb + row) * Dq + i) * 128 + col;
                    *(float2*)&g_qk[o] = make_float2(v0, v1);
                }
            }
    }
}

// ---------------------------------------------------------------------------
// Attention v2: scores + softmax only. One warp per row, 8 warps/CTA.
// Per-warp floats: QK 17*132=2244 | SC 1156 | VG 68 | pad -> 3472
// ---------------------------------------------------------------------------
#define AT_WARP 3472
#define SMEM_ATTN (8 * AT_WARP * 4)

__global__ __launch_bounds__(256) void attn_kernel(const float* __restrict__ bfc,
                                                   float* __restrict__ out) {
    float* smem = (float*)dyn_smem;
    const int lane = threadIdx.x & 31;
    const int w = threadIdx.x >> 5;
    const int b = blockIdx.x * 8 + w;

    float* QK = smem + w * AT_WARP;
    float* SC = QK + 2244;
    float* VG = SC + 1156;

    const float* src = g_qk + (size_t)b * (Dq * 128);
    for (int idx = lane; idx < Dq * 128; idx += 32)
        QK[(idx >> 7) * 132 + (idx & 127)] = src[idx];
    for (int idx = lane; idx < NHq * Dq; idx += 32)
        VG[idx] = g_vg[(size_t)b * (NHq * Dq) + idx];
    __syncwarp();

    for (int idx = lane; idx < NHq * Dq * Dq; idx += 32) {
        int h = idx / (Dq * Dq);
        int rem = idx - h * (Dq * Dq);
        int qd = rem / Dq, kd = rem - qd * Dq;
        const float4* Qp = (const float4*)(QK + qd * 132 + h * 16);
        const float4* Kp = (const float4*)(QK + kd * 132 + 64 + h * 16);
        float s = 0.f;
        #pragma unroll
        for (int c = 0; c < 4; c++) {
            float4 q4 = Qp[c], k4 = Kp[c];
            s += q4.x * k4.x + q4.y * k4.y + q4.z * k4.z + q4.w * k4.w;
        }
        SC[idx] = s;
    }
    __syncwarp();

    float part = 0.f;
    for (int idx = lane; idx < NHq * Dq; idx += 32) {
        int h = idx / Dq, qd = idx - h * Dq;
        const float* row = SC + h * (Dq * Dq) + qd * Dq;
        const float* vg = VG + h * Dq;
        float m = row[0];
        #pragma unroll
        for (int k = 1; k < Dq; k++) m = fmaxf(m, row[k]);
        float se = 0.f, dot = 0.f;
        #pragma unroll
        for (int k = 0; k < Dq; k++) {
            float e = __expf(row[k] - m);
            se += e;
            dot += e * vg[k];
        }
        part += dot / se;
    }
    #pragma unroll
    for (int off = 16; off; off >>= 1) part += __shfl_down_sync(0xffffffffu, part, off);
    if (lane == 0) out[b] = lrelu(part * (1.f / 17.f) + g_c0[0] + bfc[0]);
}

// ---------------------------------------------------------------------------
extern "C" void kernel_launch(void* const* d_in, const int* in_sizes, int n_in,
                              void* d_out, int out_size) {
    (void)in_sizes; (void)n_in; (void)out_size;
    const float* x   = (const float*)d_in[0];
    const float* W1  = (const float*)d_in[1];
    const float* b1  = (const float*)d_in[2];
    const float* Wm  = (const float*)d_in[3];
    const float* bm  = (const float*)d_in[4];
    const float* Wf  = (const float*)d_in[5];
    const float* bf  = (const float*)d_in[6];
    const float* Wq  = (const float*)d_in[7];
    const float* bq  = (const float*)d_in[8];
    const float* Wk  = (const float*)d_in[9];
    const float* bk  = (const float*)d_in[10];
    const float* Wv  = (const float*)d_in[11];
    const float* bv  = (const float*)d_in[12];
    const float* Wo  = (const float*)d_in[13];
    const float* bo  = (const float*)d_in[14];
    const float* Wfc = (const float*)d_in[15];
    const float* bfc = (const float*)d_in[16];
    float* out = (float*)d_out;

    cudaFuncSetAttribute(subnet_mma_kernel, cudaFuncAttributeMaxDynamicSharedMemorySize, SMEM_SUB);
    cudaFuncSetAttribute(attn_kernel, cudaFuncAttributeMaxDynamicSharedMemorySize, SMEM_ATTN);

    precompute_kernel<<<1, 256>>>(Wo, bo, Wfc, Wv, bv);
    pack_mid_kernel<<<34 * 256, 256>>>(Wm);
    pack_fin_kernel<<<17 * 256, 64>>>(Wf);
    pack_qk_kernel<<<34, 256>>>(Wq, Wk);
    subnet_mma_kernel<<<dim3(Bq / 128, Dq), 256, SMEM_SUB>>>(x, W1, b1, bm, bf, bq, bk);
    attn_kernel<<<Bq / 8, 256, SMEM_ATTN>>>(bfc, out);
}

// round 8
// speedup vs baseline: 4.2073x; 1.0009x over previous
#include <cuda_runtime.h>
#include <cuda_bf16.h>
#include <cstdint>

#define Bq 16384
#define Dq 17
#define Hq 256
#define Eq 64
#define NHq 4
#define SLOPE 0.01f

// ---------------------------------------------------------------------------
// Device scratch
// ---------------------------------------------------------------------------
__device__ float g_qk[(size_t)Bq * Dq * 128];                      // 142.6 MB: Q(scaled)|K
__device__ float g_vg[(size_t)Bq * NHq * Dq];                      // 4.5 MB
__device__ __align__(16) float g_wvg[NHq * Eq];
__device__ float g_bvg[NHq];
__device__ float g_c0[1];
// bf16 hi/lo split weights, [k][n] row-major
__device__ __align__(16) __nv_bfloat16 g_midHi[(size_t)34 * 65536];
__device__ __align__(16) __nv_bfloat16 g_midLo[(size_t)34 * 65536];
__device__ __align__(16) __nv_bfloat16 g_finHi[(size_t)17 * 16384];
__device__ __align__(16) __nv_bfloat16 g_finLo[(size_t)17 * 16384];
// WqkT packed: [c 0..63][n 0..135] (n<64: Wq^T, 64..127: Wk^T, pad 128..135)
__device__ __align__(16) __nv_bfloat16 g_qkHi[64 * 136];
__device__ __align__(16) __nv_bfloat16 g_qkLo[64 * 136];

__device__ __forceinline__ float lrelu(float v) { return v >= 0.f ? v : SLOPE * v; }

// ---------------------------------------------------------------------------
// mma / ldmatrix / cp.async helpers (baseline PTX, sm_80+)
// ---------------------------------------------------------------------------
__device__ __forceinline__ void ldsm4(uint32_t addr, uint32_t* r) {
    asm volatile("ldmatrix.sync.aligned.m8n8.x4.shared.b16 {%0,%1,%2,%3}, [%4];"
                 : "=r"(r[0]), "=r"(r[1]), "=r"(r[2]), "=r"(r[3]) : "r"(addr));
}
__device__ __forceinline__ void ldsm4t(uint32_t addr, uint32_t* r) {
    asm volatile("ldmatrix.sync.aligned.m8n8.x4.trans.shared.b16 {%0,%1,%2,%3}, [%4];"
                 : "=r"(r[0]), "=r"(r[1]), "=r"(r[2]), "=r"(r[3]) : "r"(addr));
}
__device__ __forceinline__ void mma_bf(float* d, const uint32_t* a, const uint32_t* b) {
    asm volatile("mma.sync.aligned.m16n8k16.row.col.f32.bf16.bf16.f32 "
                 "{%0,%1,%2,%3}, {%4,%5,%6,%7}, {%8,%9}, {%0,%1,%2,%3};"
                 : "+f"(d[0]), "+f"(d[1]), "+f"(d[2]), "+f"(d[3])
                 : "r"(a[0]), "r"(a[1]), "r"(a[2]), "r"(a[3]), "r"(b[0]), "r"(b[1]));
}
#define CP_A16(s, g) asm volatile("cp.async.ca.shared.global [%0], [%1], 16;" :: "r"(s), "l"(g))
#define CP_COMMIT()  asm volatile("cp.async.commit_group;")
#define CP_WAIT0()   asm volatile("cp.async.wait_group 0;" ::: "memory")

// SMEM layout (bytes)
#define SA_LO   67584          // hA_hi [128][264]bf16
#define WB      135168         // hA_lo ends here; W buffers start
#define WBUF    33792
#define MIDLO   16896
#define FINLO   4608
#define QKHI    (WB + 9216)            // gap in fin buffer 0
#define QKLO    (WB + WBUF + 9216)     // gap in fin buffer 1
#define SMEM_SUB 202752

extern __shared__ __align__(16) char dyn_smem[];

// ---------------------------------------------------------------------------
// Precompute folded epilogue weights (g = Wo^T Wfc; wvg, bvg, c0)
// ---------------------------------------------------------------------------
__global__ void precompute_kernel(const float* __restrict__ Wo, const float* __restrict__ bo,
                                  const float* __restrict__ Wfc, const float* __restrict__ Wv,
                                  const float* __restrict__ bv) {
    __shared__ float gs[Eq];
    int t = threadIdx.x;
    if (t < Eq) {
        float s = 0.f;
        for (int e = 0; e < Eq; e++) s += Wo[e * Eq + t] * Wfc[e];
        gs[t] = s;
    }
    if (t == Eq) {
        float s = 0.f;
        for (int e = 0; e < Eq; e++) s += bo[e] * Wfc[e];
        g_c0[0] = s;
    }
    __syncthreads();
    {
        int h = t >> 6, f = t & 63;
        float s = 0.f;
        for (int c = 0; c < 16; c++) s += Wv[(h * 16 + c) * Eq + f] * gs[h * 16 + c];
        g_wvg[t] = s;
    }
    if (t < NHq) {
        float s = 0.f;
        for (int c = 0; c < 16; c++) s += bv[t * 16 + c] * gs[t * 16 + c];
        g_bvg[t] = s;
    }
}

// ---------------------------------------------------------------------------
// Pack kernels: hi/lo bf16 splits
// ---------------------------------------------------------------------------
__global__ void pack_mid_kernel(const float* __restrict__ Wm) {
    size_t idx = (size_t)blockIdx.x * 256 + threadIdx.x;
    float w = Wm[idx];
    __nv_bfloat16 h = __float2bfloat16(w);
    g_midHi[idx] = h;
    g_midLo[idx] = __float2bfloat16(w - __bfloat162float(h));
}
__global__ void pack_fin_kernel(const float* __restrict__ Wf) {
    size_t idx = (size_t)blockIdx.x * 64 + threadIdx.x;
    float w = Wf[idx];
    __nv_bfloat16 h = __float2bfloat16(w);
    g_finHi[idx] = h;
    g_finLo[idx] = __float2bfloat16(w - __bfloat162float(h));
}
__global__ void pack_qk_kernel(const float* __restrict__ Wq, const float* __restrict__ Wk) {
    int idx = blockIdx.x * 256 + threadIdx.x;   // 64*136 = 8704
    if (idx >= 64 * 136) return;
    int c = idx / 136, n = idx % 136;
    float w = 0.f;
    if (n < 64) w = Wq[n * Eq + c];
    else if (n < 128) w = Wk[(n - 64) * Eq + c];
    __nv_bfloat16 h = __float2bfloat16(w);
    g_qkHi[idx] = h;
    g_qkLo[idx] = __float2bfloat16(w - __bfloat162float(h));
}

// ---------------------------------------------------------------------------
// cp.async loaders
// ---------------------------------------------------------------------------
__device__ __forceinline__ void issue_mid(uint32_t sb, int tid, int li, int c, int b) {
    const __nv_bfloat16* bh = g_midHi + (size_t)li * 65536 + (size_t)c * 8192;
    const __nv_bfloat16* bl = g_midLo + (size_t)li * 65536 + (size_t)c * 8192;
    #pragma unroll
    for (int j = 0; j < 8; ++j) {
        int lin = j * 256 + tid;
        int s = lin >> 10, rem = lin & 1023, row = rem >> 5, seg = rem & 31;
        const __nv_bfloat16* g = (s ? bl : bh) + row * 256 + seg * 8;
        uint32_t sa = sb + WB + (uint32_t)b * WBUF + (uint32_t)s * MIDLO +
                      (uint32_t)row * 528 + (uint32_t)seg * 16;
        CP_A16(sa, g);
    }
    CP_COMMIT();
}
__device__ __forceinline__ void issue_fin(uint32_t sb, int tid, int i, int c, int b) {
    const __nv_bfloat16* bh = g_finHi + (size_t)i * 16384 + (size_t)c * 2048;
    const __nv_bfloat16* bl = g_finLo + (size_t)i * 16384 + (size_t)c * 2048;
    #pragma unroll
    for (int j = 0; j < 2; ++j) {
        int lin = j * 256 + tid;
        int s = lin >> 8, rem = lin & 255, row = rem >> 3, seg = rem & 7;
        const __nv_bfloat16* g = (s ? bl : bh) + row * 64 + seg * 8;
        uint32_t sa = sb + WB + (uint32_t)b * WBUF + (uint32_t)s * FINLO +
                      (uint32_t)row * 144 + (uint32_t)seg * 16;
        CP_A16(sa, g);
    }
    CP_COMMIT();
}
__device__ __forceinline__ void issue_qk(uint32_t sb, int tid) {
    #pragma unroll
    for (int j = 0; j < 9; ++j) {
        int lin = j * 256 + tid;
        if (lin < 2176) {
            int s = lin >= 1088;
            int rem = s ? lin - 1088 : lin;
            int row = rem / 17, seg = rem % 17;
            const __nv_bfloat16* g = (s ? g_qkLo : g_qkHi) + row * 136 + seg * 8;
            uint32_t sa = sb + (uint32_t)(s ? QKLO : QKHI) +
                          (uint32_t)row * 272 + (uint32_t)seg * 16;
            CP_A16(sa, g);
        }
    }
    CP_COMMIT();
}

// ---------------------------------------------------------------------------
// Subnet: grid (128, 17), 256 threads. Layers 0..2 + fused QK projection.
// ---------------------------------------------------------------------------
__global__ __launch_bounds__(256, 1)
void subnet_mma_kernel(const float* __restrict__ x, const float* __restrict__ W1,
                       const float* __restrict__ b1, const float* __restrict__ bm,
                       const float* __restrict__ bf, const float* __restrict__ bq,
                       const float* __restrict__ bk) {
    char* smem = dyn_smem;
    const uint32_t sb = (uint32_t)__cvta_generic_to_shared(smem);
    const int i = blockIdx.y;
    const int rb = blockIdx.x * 128;
    const int tid = threadIdx.x, wid = tid >> 5, lane = tid & 31;
    const int qr = ((lane >> 3) & 1) * 8 + (lane & 7);
    const int qc = (lane >> 4) * 8;
    const uint32_t thA = (uint32_t)qr * 528 + (uint32_t)qc * 2;
    const uint32_t thWf = (uint32_t)qr * 144 + (uint32_t)qc * 2;
    const uint32_t thQK = (uint32_t)qr * 272 + (uint32_t)qc * 2;
    const int r0 = (wid >> 2) * 64, n0 = (wid & 3) * 64;
    const int r0f = wid * 16;
    const int erow = lane >> 2, ecol = (lane & 3) * 2;

    issue_mid(sb, tid, i, 0, 0);

    // ---- Layer 0 ----
    {
        int r = tid >> 1, cb = (tid & 1) * 128;
        float xv = x[(size_t)(rb + r) * Dq + i];
        const float* w1 = W1 + i * Hq;
        const float* bb = b1 + i * Hq;
        char* rowp = smem + (size_t)r * 528 + (size_t)cb * 2;
        #pragma unroll 8
        for (int c = 0; c < 128; c += 2) {
            float v0 = lrelu(fmaf(xv, w1[cb + c], bb[cb + c]));
            float v1 = lrelu(fmaf(xv, w1[cb + c + 1], bb[cb + c + 1]));
            __nv_bfloat16 h0 = __float2bfloat16(v0), h1 = __float2bfloat16(v1);
            uint32_t hw = ((uint32_t)__bfloat16_as_ushort(h1) << 16) |
                          (uint32_t)__bfloat16_as_ushort(h0);
            __nv_bfloat16 e0 = __float2bfloat16(v0 - __bfloat162float(h0));
            __nv_bfloat16 e1 = __float2bfloat16(v1 - __bfloat162float(h1));
            uint32_t lw = ((uint32_t)__bfloat16_as_ushort(e1) << 16) |
                          (uint32_t)__bfloat16_as_ushort(e0);
            *(uint32_t*)(rowp + c * 2) = hw;
            *(uint32_t*)(rowp + SA_LO + c * 2) = lw;
        }
    }

    for (int l = 0; l < 3; ++l) {
        float acc[4][8][4];
        #pragma unroll
        for (int a = 0; a < 4; ++a)
            #pragma unroll
            for (int b = 0; b < 8; ++b)
                #pragma unroll
                for (int q = 0; q < 4; ++q) acc[a][b][q] = 0.f;

        for (int c = 0; c < 8; ++c) {
            CP_WAIT0();
            __syncthreads();
            if (c < 7) {
                if (l < 2) issue_mid(sb, tid, l * 17 + i, c + 1, (c + 1) & 1);
                else       issue_fin(sb, tid, i, c + 1, (c + 1) & 1);
            }
            const uint32_t wb = sb + WB + (uint32_t)(c & 1) * WBUF;

            if (l < 2) {
                #pragma unroll
                for (int ks = 0; ks < 2; ++ks) {
                    uint32_t ah[4][4], bh[4][4];
                    const uint32_t abase = sb + (uint32_t)r0 * 528 +
                                           (uint32_t)(c * 32 + ks * 16) * 2 + thA;
                    #pragma unroll
                    for (int mi = 0; mi < 4; ++mi) ldsm4(abase + mi * 8448, ah[mi]);
                    const uint32_t bbase = wb + (uint32_t)(ks * 16) * 528 +
                                           (uint32_t)n0 * 2 + thA;
                    #pragma unroll
                    for (int nj = 0; nj < 4; ++nj) ldsm4t(bbase + nj * 32, bh[nj]);
                    #pragma unroll
                    for (int mi = 0; mi < 4; ++mi)
                        #pragma unroll
                        for (int nj = 0; nj < 4; ++nj) {
                            mma_bf(acc[mi][2 * nj], ah[mi], bh[nj]);
                            mma_bf(acc[mi][2 * nj + 1], ah[mi], bh[nj] + 2);
                        }
                    #pragma unroll
                    for (int nj = 0; nj < 4; ++nj) {
                        uint32_t bl[4];
                        ldsm4t(bbase + MIDLO + nj * 32, bl);
                        #pragma unroll
                        for (int mi = 0; mi < 4; ++mi) {
                            mma_bf(acc[mi][2 * nj], ah[mi], bl);
                            mma_bf(acc[mi][2 * nj + 1], ah[mi], bl + 2);
                        }
                    }
                    #pragma unroll
                    for (int mi = 0; mi < 4; ++mi) {
                        uint32_t al[4];
                        ldsm4(abase + SA_LO + mi * 8448, al);
                        #pragma unroll
                        for (int nj = 0; nj < 4; ++nj) {
                            mma_bf(acc[mi][2 * nj], al, bh[nj]);
                            mma_bf(acc[mi][2 * nj + 1], al, bh[nj] + 2);
                        }
                    }
                }
            } else {
                #pragma unroll
                for (int ks = 0; ks < 2; ++ks) {
                    uint32_t ah[4], al[4], bh[4][4];
                    const uint32_t abase = sb + (uint32_t)r0f * 528 +
                                           (uint32_t)(c * 32 + ks * 16) * 2 + thA;
                    ldsm4(abase, ah);
                    ldsm4(abase + SA_LO, al);
                    const uint32_t bbase = wb + (uint32_t)(ks * 16) * 144 + thWf;
                    #pragma unroll
                    for (int nj = 0; nj < 4; ++nj) ldsm4t(bbase + nj * 32, bh[nj]);
                    #pragma unroll
                    for (int nj = 0; nj < 4; ++nj) {
                        mma_bf(acc[0][2 * nj], ah, bh[nj]);
                        mma_bf(acc[0][2 * nj + 1], ah, bh[nj] + 2);
                        mma_bf(acc[0][2 * nj], al, bh[nj]);
                        mma_bf(acc[0][2 * nj + 1], al, bh[nj] + 2);
                        uint32_t bl[4];
                        ldsm4t(bbase + FINLO + nj * 32, bl);
                        mma_bf(acc[0][2 * nj], ah, bl);
                        mma_bf(acc[0][2 * nj + 1], ah, bl + 2);
                    }
                }
            }
            __syncthreads();
        }

        if (l < 2) {
            if (l == 0) {
                issue_mid(sb, tid, 17 + i, 0, 0);
            } else {
                issue_fin(sb, tid, i, 0, 0);
                issue_qk(sb, tid);
            }
            const float* bmL = bm + (size_t)(l * 17 + i) * 256;
            #pragma unroll
            for (int mi = 0; mi < 4; ++mi)
                #pragma unroll
                for (int ni = 0; ni < 8; ++ni) {
                    int col = n0 + ni * 8 + ecol;
                    float b0v = bmL[col], b1v = bmL[col + 1];
                    #pragma unroll
                    for (int half = 0; half < 2; ++half) {
                        int row = r0 + mi * 16 + erow + half * 8;
                        float v0 = lrelu(acc[mi][ni][half * 2] + b0v);
                        float v1 = lrelu(acc[mi][ni][half * 2 + 1] + b1v);
                        __nv_bfloat16 h0 = __float2bfloat16(v0), h1 = __float2bfloat16(v1);
                        uint32_t hw = ((uint32_t)__bfloat16_as_ushort(h1) << 16) |
                                      (uint32_t)__bfloat16_as_ushort(h0);
                        __nv_bfloat16 e0 = __float2bfloat16(v0 - __bfloat162float(h0));
                        __nv_bfloat16 e1 = __float2bfloat16(v1 - __bfloat162float(h1));
                        uint32_t lw = ((uint32_t)__bfloat16_as_ushort(e1) << 16) |
                                      (uint32_t)__bfloat16_as_ushort(e0);
                        char* p = smem + (size_t)row * 528 + (size_t)col * 2;
                        *(uint32_t*)p = hw;
                        *(uint32_t*)(p + SA_LO) = lw;
                    }
                }
            __syncthreads();
        } else {
            // ---- fin epilogue: + bias; vg via 4-lane reduce; tokens -> SMEM bf16 ----
            const float* bfL = bf + i * Eq;
            float pvg[2][NHq];
            #pragma unroll
            for (int h = 0; h < NHq; ++h) { pvg[0][h] = 0.f; pvg[1][h] = 0.f; }
            #pragma unroll
            for (int ni = 0; ni < 8; ++ni) {
                int col = ni * 8 + ecol;
                float b0v = bfL[col], b1v = bfL[col + 1];
                acc[0][ni][0] += b0v; acc[0][ni][1] += b1v;
                acc[0][ni][2] += b0v; acc[0][ni][3] += b1v;
                #pragma unroll
                for (int h = 0; h < NHq; ++h) {
                    float w0 = g_wvg[h * Eq + col], w1 = g_wvg[h * Eq + col + 1];
                    pvg[0][h] += acc[0][ni][0] * w0 + acc[0][ni][1] * w1;
                    pvg[1][h] += acc[0][ni][2] * w0 + acc[0][ni][3] * w1;
                }
            }
            #pragma unroll
            for (int h = 0; h < NHq; ++h) {
                #pragma unroll
                for (int off = 1; off < 4; off <<= 1) {
                    pvg[0][h] += __shfl_xor_sync(0xffffffffu, pvg[0][h], off);
                    pvg[1][h] += __shfl_xor_sync(0xffffffffu, pvg[1][h], off);
                }
            }
            {
                int h = lane & 3;
                float bvgh = g_bvg[h];
                size_t base0 = ((size_t)(rb + r0f + erow) * NHq + h) * Dq + i;
                size_t base1 = ((size_t)(rb + r0f + erow + 8) * NHq + h) * Dq + i;
                g_vg[base0] = pvg[0][h] + bvgh;
                g_vg[base1] = pvg[1][h] + bvgh;
            }
            // tokens (fp32 w/ bias) -> bf16 hi/lo into A region cols 0..63
            #pragma unroll
            for (int ni = 0; ni < 8; ++ni) {
                int col = ni * 8 + ecol;
                #pragma unroll
                for (int half = 0; half < 2; ++half) {
                    int row = r0f + erow + half * 8;
                    float v0 = acc[0][ni][half * 2];
                    float v1 = acc[0][ni][half * 2 + 1];
                    __nv_bfloat16 h0 = __float2bfloat16(v0), h1 = __float2bfloat16(v1);
                    uint32_t hw = ((uint32_t)__bfloat16_as_ushort(h1) << 16) |
                                  (uint32_t)__bfloat16_as_ushort(h0);
                    __nv_bfloat16 e0 = __float2bfloat16(v0 - __bfloat162float(h0));
                    __nv_bfloat16 e1 = __float2bfloat16(v1 - __bfloat162float(h1));
                    uint32_t lw = ((uint32_t)__bfloat16_as_ushort(e1) << 16) |
                                  (uint32_t)__bfloat16_as_ushort(e0);
                    char* p = smem + (size_t)row * 528 + (size_t)col * 2;
                    *(uint32_t*)p = hw;
                    *(uint32_t*)(p + SA_LO) = lw;
                }
            }
            __syncthreads();
        }
    }

    // ---- QK projection GEMM: [128x64] @ [64x128], bf16x3 ----
    {
        const int r0p = (wid >> 2) * 64, n0p = (wid & 3) * 32;
        float acc2[4][4][4];
        #pragma unroll
        for (int a = 0; a < 4; ++a)
            #pragma unroll
            for (int b = 0; b < 4; ++b)
                #pragma unroll
                for (int q = 0; q < 4; ++q) acc2[a][b][q] = 0.f;

        #pragma unroll
        for (int ks = 0; ks < 4; ++ks) {
            uint32_t ah[4][4], bh[2][4];
            const uint32_t abase = sb + (uint32_t)r0p * 528 + (uint32_t)(ks * 16) * 2 + thA;
            #pragma unroll
            for (int mi = 0; mi < 4; ++mi) ldsm4(abase + mi * 8448, ah[mi]);
            const uint32_t bbase = sb + QKHI + (uint32_t)(ks * 16) * 272 +
                                   (uint32_t)n0p * 2 + thQK;
            #pragma unroll
            for (int nj = 0; nj < 2; ++nj) ldsm4t(bbase + nj * 32, bh[nj]);
            #pragma unroll
            for (int mi = 0; mi < 4; ++mi)
                #pragma unroll
                for (int nj = 0; nj < 2; ++nj) {
                    mma_bf(acc2[mi][2 * nj], ah[mi], bh[nj]);
                    mma_bf(acc2[mi][2 * nj + 1], ah[mi], bh[nj] + 2);
                }
            #pragma unroll
            for (int nj = 0; nj < 2; ++nj) {
                uint32_t bl[4];
                ldsm4t(bbase + (QKLO - QKHI) + nj * 32, bl);
                #pragma unroll
                for (int mi = 0; mi < 4; ++mi) {
                    mma_bf(acc2[mi][2 * nj], ah[mi], bl);
                    mma_bf(acc2[mi][2 * nj + 1], ah[mi], bl + 2);
                }
            }
            #pragma unroll
            for (int mi = 0; mi < 4; ++mi) {
                uint32_t al[4];
                ldsm4(abase + SA_LO + mi * 8448, al);
                #pragma unroll
                for (int nj = 0; nj < 2; ++nj) {
                    mma_bf(acc2[mi][2 * nj], al, bh[nj]);
                    mma_bf(acc2[mi][2 * nj + 1], al, bh[nj] + 2);
                }
            }
        }
        // epilogue: Q=(v+bq)*0.25 (cols<64), K=v+bk
        #pragma unroll
        for (int mi = 0; mi < 4; ++mi)
            #pragma unroll
            for (int ni = 0; ni < 4; ++ni) {
                int col = n0p + ni * 8 + ecol;
                float bb0, bb1, sc;
                if (col < 64) { bb0 = bq[col]; bb1 = bq[col + 1]; sc = 0.25f; }
                else          { bb0 = bk[col - 64]; bb1 = bk[col - 63]; sc = 1.f; }
                #pragma unroll
                for (int half = 0; half < 2; ++half) {
                    int row = r0p + mi * 16 + erow + half * 8;
                    float v0 = (acc2[mi][ni][half * 2] + bb0) * sc;
                    float v1 = (acc2[mi][ni][half * 2 + 1] + bb1) * sc;
                    size_t o = ((size_t)(rb + row) * Dq + i) * 128 + col;
                    *(float2*)&g_qk[o] = make_float2(v0, v1);
                }
            }
    }
}

// ---------------------------------------------------------------------------
// Attention v2: scores + softmax only. One warp per row, 8 warps/CTA.
// Per-warp floats: QK 17*132=2244 | SC 1156 | VG 68 | pad -> 3472
// ---------------------------------------------------------------------------
#define AT_WARP 3472
#define SMEM_ATTN (8 * AT_WARP * 4)

__global__ __launch_bounds__(256) void attn_kernel(const float* __restrict__ bfc,
                                                   float* __restrict__ out) {
    float* smem = (float*)dyn_smem;
    const int lane = threadIdx.x & 31;
    const int w = threadIdx.x >> 5;
    const int b = blockIdx.x * 8 + w;

    float* QK = smem + w * AT_WARP;
    float* SC = QK + 2244;
    float* VG = SC + 1156;

    const float* src = g_qk + (size_t)b * (Dq * 128);
    for (int idx = lane; idx < Dq * 128; idx += 32)
        QK[(idx >> 7) * 132 + (idx & 127)] = src[idx];
    for (int idx = lane; idx < NHq * Dq; idx += 32)
        VG[idx] = g_vg[(size_t)b * (NHq * Dq) + idx];
    __syncwarp();

    for (int idx = lane; idx < NHq * Dq * Dq; idx += 32) {
        int h = idx / (Dq * Dq);
        int rem = idx - h * (Dq * Dq);
        int qd = rem / Dq, kd = rem - qd * Dq;
        const float4* Qp = (const float4*)(QK + qd * 132 + h * 16);
        const float4* Kp = (const float4*)(QK + kd * 132 + 64 + h * 16);
        float s = 0.f;
        #pragma unroll
        for (int c = 0; c < 4; c++) {
            float4 q4 = Qp[c], k4 = Kp[c];
            s += q4.x * k4.x + q4.y * k4.y + q4.z * k4.z + q4.w * k4.w;
        }
        SC[idx] = s;
    }
    __syncwarp();

    float part = 0.f;
    for (int idx = lane; idx < NHq * Dq; idx += 32) {
        int h = idx / Dq, qd = idx - h * Dq;
        const float* row = SC + h * (Dq * Dq) + qd * Dq;
        const float* vg = VG + h * Dq;
        float m = row[0];
        #pragma unroll
        for (int k = 1; k < Dq; k++) m = fmaxf(m, row[k]);
        float se = 0.f, dot = 0.f;
        #pragma unroll
        for (int k = 0; k < Dq; k++) {
            float e = __expf(row[k] - m);
            se += e;
            dot += e * vg[k];
        }
        part += dot / se;
    }
    #pragma unroll
    for (int off = 16; off; off >>= 1) part += __shfl_down_sync(0xffffffffu, part, off);
    if (lane == 0) out[b] = lrelu(part * (1.f / 17.f) + g_c0[0] + bfc[0]);
}

// ---------------------------------------------------------------------------
extern "C" void kernel_launch(void* const* d_in, const int* in_sizes, int n_in,
                              void* d_out, int out_size) {
    (void)in_sizes; (void)n_in; (void)out_size;
    const float* x   = (const float*)d_in[0];
    const float* W1  = (const float*)d_in[1];
    const float* b1  = (const float*)d_in[2];
    const float* Wm  = (const float*)d_in[3];
    const float* bm  = (const float*)d_in[4];
    const float* Wf  = (const float*)d_in[5];
    const float* bf  = (const float*)d_in[6];
    const float* Wq  = (const float*)d_in[7];
    const float* bq  = (const float*)d_in[8];
    const float* Wk  = (const float*)d_in[9];
    const float* bk  = (const float*)d_in[10];
    const float* Wv  = (const float*)d_in[11];
    const float* bv  = (const float*)d_in[12];
    const float* Wo  = (const float*)d_in[13];
    const float* bo  = (const float*)d_in[14];
    const float* Wfc = (const float*)d_in[15];
    const float* bfc = (const float*)d_in[16];
    float* out = (float*)d_out;

    cudaFuncSetAttribute(subnet_mma_kernel, cudaFuncAttributeMaxDynamicSharedMemorySize, SMEM_SUB);
    cudaFuncSetAttribute(attn_kernel, cudaFuncAttributeMaxDynamicSharedMemorySize, SMEM_ATTN);

    precompute_kernel<<<1, 256>>>(Wo, bo, Wfc, Wv, bv);
    pack_mid_kernel<<<34 * 256, 256>>>(Wm);
    pack_fin_kernel<<<17 * 256, 64>>>(Wf);
    pack_qk_kernel<<<34, 256>>>(Wq, Wk);
    subnet_mma_kernel<<<dim3(Bq / 128, Dq), 256, SMEM_SUB>>>(x, W1, b1, bm, bf, bq, bk);
    attn_kernel<<<Bq / 8, 256, SMEM_ATTN>>>(bfc, out);
}